// round 7
// baseline (speedup 1.0000x reference)
#include <cuda_runtime.h>
#include <cstdint>

typedef unsigned long long ULL;

__device__ __forceinline__ ULL pack2(float lo, float hi) {
    ULL r; asm("mov.b64 %0, {%1, %2};" : "=l"(r) : "f"(lo), "f"(hi)); return r;
}
__device__ __forceinline__ ULL splat2(float v) {
    ULL r; asm("mov.b64 %0, {%1, %1};" : "=l"(r) : "f"(v)); return r;
}
__device__ __forceinline__ void unpack2(ULL v, float& lo, float& hi) {
    asm("mov.b64 {%0, %1}, %2;" : "=f"(lo), "=f"(hi) : "l"(v));
}
__device__ __forceinline__ ULL fma2(ULL a, ULL b, ULL c) {
    ULL d; asm("fma.rn.f32x2 %0, %1, %2, %3;" : "=l"(d) : "l"(a), "l"(b), "l"(c)); return d;
}

#define NN 256

// partial Hsum: slot [half][node][h]
__device__ float g_Hs[2 * 1024 * 64];

// ============================================================================
// K1: grid 2048 = (node, half); 128 i-rows/block (2 chunks of 64).
// Thread = (ii in 16, hp in 8); each thread: 4 h-pair chains {hp+8p, hp+8p+32}.
// e stored RAW (32B rows), read as LDS.128, splatted via alu movs.
// ============================================================================
__global__ __launch_bounds__(128, 4)
void k_edge(const float* __restrict__ edge,
            const float* __restrict__ W1,
            const float* __restrict__ b1) {
    __shared__ float es[2][64 * 8];    // raw rows, 32B pitch
    __shared__ float w1s[512];
    __shared__ float hsum[64];

    const int t    = threadIdx.x;
    const int bx   = blockIdx.x;
    const int node = bx >> 1;
    const int half = bx & 1;
    const int j    = node & 255;
    const int b    = node >> 8;

    if (t < 64) hsum[t] = 0.f;
    #pragma unroll
    for (int r = 0; r < 4; r++) w1s[t + 128 * r] = W1[t + 128 * r];

    const int ii = t >> 3;     // 16 i-groups (4 rows each per chunk)
    const int hp = t & 7;      // 8 h-slots -> pairs {hp+8p, hp+8p+32}, p=0..3

    // loader: thread t stages row (t>>1), float4 half q = t&1
    const int lrow = t >> 1, q = t & 1;
    const float4* src = reinterpret_cast<const float4*>(edge)
                        + ((ULL)(b * NN) * NN + j) * 2 + q
                        + (ULL)(half * 128) * 512;          // +512 float4 per i

    float4 v0 = src[(ULL)lrow * 512];
    *(float4*)&es[0][lrow * 8 + q * 4] = v0;
    float4 v1 = src[(ULL)(64 + lrow) * 512];   // prefetch chunk 1
    __syncthreads();                            // hsum + w1s + chunk0 ready

    ULL w12[4][8], b2i[4];
    #pragma unroll
    for (int p = 0; p < 4; p++) {
        const int h0 = hp + 8 * p;
        b2i[p] = pack2(b1[h0], b1[h0 + 32]);
        #pragma unroll
        for (int f = 0; f < 8; f++)
            w12[p][f] = pack2(w1s[f * 64 + h0], w1s[f * 64 + h0 + 32]);
    }

    const ULL HMASK = 0x7FFFFFFF7FFFFFFFULL;
    const ULL HALF2 = pack2(0.5f, 0.5f);
    ULL acc[4];
    #pragma unroll
    for (int p = 0; p < 4; p++) acc[p] = pack2(0.f, 0.f);

    #pragma unroll 1
    for (int c = 0; c < 2; c++) {
        const float* ebuf = es[c];
        #pragma unroll
        for (int s = 0; s < 4; s++) {
            const float* er = &ebuf[(s * 16 + ii) * 8];
            float4 ea = *(const float4*)&er[0];
            float4 eb4 = *(const float4*)&er[4];
            ULL e0 = splat2(ea.x),  e1 = splat2(ea.y);
            ULL e2 = splat2(ea.z),  e3 = splat2(ea.w);
            ULL e4 = splat2(eb4.x), e5 = splat2(eb4.y);
            ULL e6 = splat2(eb4.z), e7 = splat2(eb4.w);

            ULL h0 = fma2(e0, w12[0][0], b2i[0]);
            ULL h1 = fma2(e0, w12[1][0], b2i[1]);
            ULL h2 = fma2(e0, w12[2][0], b2i[2]);
            ULL h3 = fma2(e0, w12[3][0], b2i[3]);
            h0 = fma2(e1, w12[0][1], h0); h1 = fma2(e1, w12[1][1], h1);
            h2 = fma2(e1, w12[2][1], h2); h3 = fma2(e1, w12[3][1], h3);
            h0 = fma2(e2, w12[0][2], h0); h1 = fma2(e2, w12[1][2], h1);
            h2 = fma2(e2, w12[2][2], h2); h3 = fma2(e2, w12[3][2], h3);
            h0 = fma2(e3, w12[0][3], h0); h1 = fma2(e3, w12[1][3], h1);
            h2 = fma2(e3, w12[2][3], h2); h3 = fma2(e3, w12[3][3], h3);
            h0 = fma2(e4, w12[0][4], h0); h1 = fma2(e4, w12[1][4], h1);
            h2 = fma2(e4, w12[2][4], h2); h3 = fma2(e4, w12[3][4], h3);
            h0 = fma2(e5, w12[0][5], h0); h1 = fma2(e5, w12[1][5], h1);
            h2 = fma2(e5, w12[2][5], h2); h3 = fma2(e5, w12[3][5], h3);
            h0 = fma2(e6, w12[0][6], h0); h1 = fma2(e6, w12[1][6], h1);
            h2 = fma2(e6, w12[2][6], h2); h3 = fma2(e6, w12[3][6], h3);
            h0 = fma2(e7, w12[0][7], h0); h1 = fma2(e7, w12[1][7], h1);
            h2 = fma2(e7, w12[2][7], h2); h3 = fma2(e7, w12[3][7], h3);

            ULL a0 = h0 & HMASK, a1 = h1 & HMASK;
            ULL a2 = h2 & HMASK, a3 = h3 & HMASK;
            acc[0] = fma2(h0, HALF2, acc[0]); acc[0] = fma2(a0, HALF2, acc[0]);
            acc[1] = fma2(h1, HALF2, acc[1]); acc[1] = fma2(a1, HALF2, acc[1]);
            acc[2] = fma2(h2, HALF2, acc[2]); acc[2] = fma2(a2, HALF2, acc[2]);
            acc[3] = fma2(h3, HALF2, acc[3]); acc[3] = fma2(a3, HALF2, acc[3]);
        }

        if (c == 0) {
            *(float4*)&es[1][lrow * 8 + q * 4] = v1;
            __syncthreads();
        }
    }

    // reduce over ii: lane bits 3,4 (ii&3) via shfl, cross-warp via atomics
    float r[8];
    #pragma unroll
    for (int p = 0; p < 4; p++) unpack2(acc[p], r[2 * p], r[2 * p + 1]);
    #pragma unroll
    for (int k = 0; k < 8; k++) {
        r[k] += __shfl_xor_sync(0xffffffffu, r[k], 8);
        r[k] += __shfl_xor_sync(0xffffffffu, r[k], 16);
    }
    if ((t & 24) == 0) {
        #pragma unroll
        for (int p = 0; p < 4; p++) {
            atomicAdd(&hsum[hp + 8 * p],      r[2 * p]);
            atomicAdd(&hsum[hp + 8 * p + 32], r[2 * p + 1]);
        }
    }
    __syncthreads();
    if (t < 64) g_Hs[(half * 1024 + node) * 64 + t] = hsum[t];
}

// ============================================================================
// K2: grid 128 x 256 threads, 8 nodes/block (one wave).
// Thread = (h-half ph, colpair cp). W2 slice register-resident (one LDG burst),
// 8 independent 32-deep fma2 chains; hs read as LDS.128 (2 packed ULLs).
// ============================================================================
__global__ __launch_bounds__(256, 2)
void k_node(const float* __restrict__ x,
            const float* __restrict__ W2,
            const float* __restrict__ b2,
            const float* __restrict__ root,
            float* __restrict__ out) {
    __shared__ ULL   hs2[8 * 64];     // [node][h] splatted
    __shared__ float wpart[8 * 256];  // ph==0 partials
    __shared__ float wsf[8 * 256];
    __shared__ float rb[256];
    __shared__ float xs[128];

    const int t     = threadIdx.x;
    const int node0 = blockIdx.x * 8;
    const int cp    = t & 127;
    const int ph    = t >> 7;

    #pragma unroll
    for (int r = 0; r < 2; r++) {
        int idx = t + 256 * r;
        float hv = g_Hs[node0 * 64 + idx] + g_Hs[1024 * 64 + node0 * 64 + idx];
        hs2[idx] = pack2(hv, hv);
    }
    rb[t] = 256.f * b2[t] + root[t];
    if (t < 128) xs[t] = x[node0 * 16 + t];

    // W2 slice -> registers: h = ph*32 + k, cols {2cp, 2cp+1}
    ULL w2r[32];
    {
        const ULL* w2g = reinterpret_cast<const ULL*>(W2) + (ULL)(ph * 32) * 128 + cp;
        #pragma unroll
        for (int k = 0; k < 32; k++) w2r[k] = w2g[(ULL)k * 128];
    }
    __syncthreads();

    ULL acc[8];
    #pragma unroll
    for (int n = 0; n < 8; n++) acc[n] = pack2(0.f, 0.f);

    #pragma unroll 4
    for (int k = 0; k < 32; k += 2) {
        const int hh = ph * 32 + k;
        #pragma unroll
        for (int n = 0; n < 8; n++) {
            ulonglong2 hv = *(const ulonglong2*)&hs2[n * 64 + hh];
            acc[n] = fma2(hv.x, w2r[k],     acc[n]);
            acc[n] = fma2(hv.y, w2r[k + 1], acc[n]);
        }
    }

    if (ph == 0) {
        #pragma unroll
        for (int n = 0; n < 8; n++) {
            float lo, hi; unpack2(acc[n], lo, hi);
            wpart[n * 256 + 2 * cp]     = lo;
            wpart[n * 256 + 2 * cp + 1] = hi;
        }
    }
    __syncthreads();
    if (ph == 1) {
        #pragma unroll
        for (int n = 0; n < 8; n++) {
            float lo, hi; unpack2(acc[n], lo, hi);
            wsf[n * 256 + 2 * cp]     = lo + wpart[n * 256 + 2 * cp]     + rb[2 * cp];
            wsf[n * 256 + 2 * cp + 1] = hi + wpart[n * 256 + 2 * cp + 1] + rb[2 * cp + 1];
        }
    }
    __syncthreads();

    // x-contraction: 128 threads = 8 nodes x 16 d
    if (t < 128) {
        const int n = t >> 4, d = t & 15;
        float o = 0.f;
        #pragma unroll
        for (int c = 0; c < 16; c++)
            o += xs[n * 16 + c] * wsf[n * 256 + c * 16 + d];
        out[(node0 + n) * 16 + d] = o;
    }
}

extern "C" void kernel_launch(void* const* d_in, const int* in_sizes, int n_in,
                              void* d_out, int out_size) {
    const float* node_attr = (const float*)d_in[0];
    const float* edge_adj  = (const float*)d_in[1];
    const float* W1        = (const float*)d_in[2];
    const float* b1        = (const float*)d_in[3];
    const float* W2        = (const float*)d_in[4];
    const float* b2        = (const float*)d_in[5];
    const float* root      = (const float*)d_in[6];
    float* out = (float*)d_out;

    k_edge<<<2048, 128>>>(edge_adj, W1, b1);
    k_node<<<128, 256>>>(node_attr, W2, b2, root, out);
}

// round 8
// speedup vs baseline: 1.2220x; 1.2220x over previous
#include <cuda_runtime.h>
#include <cstdint>

typedef unsigned long long ULL;

__device__ __forceinline__ ULL pack2(float lo, float hi) {
    ULL r; asm("mov.b64 %0, {%1, %2};" : "=l"(r) : "f"(lo), "f"(hi)); return r;
}
__device__ __forceinline__ void unpack2(ULL v, float& lo, float& hi) {
    asm("mov.b64 {%0, %1}, %2;" : "=f"(lo), "=f"(hi) : "l"(v));
}
__device__ __forceinline__ ULL fma2(ULL a, ULL b, ULL c) {
    ULL d; asm("fma.rn.f32x2 %0, %1, %2, %3;" : "=l"(d) : "l"(a), "l"(b), "l"(c)); return d;
}

#define NN 256

// partial Hsum: slot [half][node][h]
__device__ float g_Hs[2 * 1024 * 64];

// swizzled row offset (floats): rows r and r+8 land in disjoint bank windows;
// offsets stay 16B-aligned (multiples of 4 floats) for LDS.128 reads.
__device__ __forceinline__ int rowoff(int r) { return r * 20 + ((r >> 3) & 1) * 4; }

// ============================================================================
// K1: grid 2048 = (node, half). 128 i-rows per block (2 chunks of 64).
// R6 structure; e-row reads widened LDS.64 x8 -> LDS.128 x4 (halves LDS wf).
// ============================================================================
__global__ __launch_bounds__(128, 6)
void k_edge(const float* __restrict__ edge,
            const float* __restrict__ W1,
            const float* __restrict__ b1) {
    __shared__ float es[2][64 * 20 + 8];
    __shared__ float w1s[512];
    __shared__ float hsum[64];

    const int t    = threadIdx.x;
    const int bx   = blockIdx.x;
    const int node = bx >> 1;
    const int half = bx & 1;
    const int j    = node & 255;
    const int b    = node >> 8;

    if (t < 64) hsum[t] = 0.f;
    #pragma unroll
    for (int r = 0; r < 4; r++) w1s[t + 128 * r] = W1[t + 128 * r];

    const int ii = t >> 4;     // 8 i-groups of 8 rows
    const int hp = t & 15;     // h pairs {hp,hp+32}, {hp+16,hp+48}

    const int il = t >> 1, q = t & 1;
    const float4* src = reinterpret_cast<const float4*>(edge)
                        + ((ULL)(b * NN) * NN + j) * 2 + q
                        + (ULL)(half * 128) * 512;          // +512 float4 per i

    float4 v0 = src[(ULL)il * 512];
    {   // stage chunk 0 (duplicated pairs)
        float* d = &es[0][rowoff(il) + q * 8];
        *(float2*)&d[0] = make_float2(v0.x, v0.x);
        *(float2*)&d[2] = make_float2(v0.y, v0.y);
        *(float2*)&d[4] = make_float2(v0.z, v0.z);
        *(float2*)&d[6] = make_float2(v0.w, v0.w);
    }
    float4 v1 = src[(ULL)(64 + il) * 512];   // prefetch chunk 1
    __syncthreads();

    ULL w12[2][8], b2i[2];
    #pragma unroll
    for (int p = 0; p < 2; p++) {
        const int h0 = hp + p * 16;
        b2i[p] = pack2(b1[h0], b1[h0 + 32]);
        #pragma unroll
        for (int f = 0; f < 8; f++)
            w12[p][f] = pack2(w1s[f * 64 + h0], w1s[f * 64 + h0 + 32]);
    }

    const ULL HMASK = 0x7FFFFFFF7FFFFFFFULL;
    const ULL HALF2 = pack2(0.5f, 0.5f);
    ULL acc0 = pack2(0.f, 0.f), acc1 = acc0;

    #pragma unroll 1
    for (int c = 0; c < 2; c++) {
        const float* eb = es[c];
        #pragma unroll
        for (int s = 0; s < 8; s++) {
            const ULL* ep = (const ULL*)&eb[rowoff(ii * 8 + s)];
            ulonglong2 p01 = *(const ulonglong2*)&ep[0];   // LDS.128
            ulonglong2 p23 = *(const ulonglong2*)&ep[2];
            ulonglong2 p45 = *(const ulonglong2*)&ep[4];
            ulonglong2 p67 = *(const ulonglong2*)&ep[6];
            ULL e0 = p01.x, e1 = p01.y, e2 = p23.x, e3 = p23.y;
            ULL e4 = p45.x, e5 = p45.y, e6 = p67.x, e7 = p67.y;

            ULL h0 = fma2(e0, w12[0][0], b2i[0]);
            ULL h1 = fma2(e0, w12[1][0], b2i[1]);
            h0 = fma2(e1, w12[0][1], h0);  h1 = fma2(e1, w12[1][1], h1);
            h0 = fma2(e2, w12[0][2], h0);  h1 = fma2(e2, w12[1][2], h1);
            h0 = fma2(e3, w12[0][3], h0);  h1 = fma2(e3, w12[1][3], h1);
            h0 = fma2(e4, w12[0][4], h0);  h1 = fma2(e4, w12[1][4], h1);
            h0 = fma2(e5, w12[0][5], h0);  h1 = fma2(e5, w12[1][5], h1);
            h0 = fma2(e6, w12[0][6], h0);  h1 = fma2(e6, w12[1][6], h1);
            h0 = fma2(e7, w12[0][7], h0);  h1 = fma2(e7, w12[1][7], h1);

            ULL a0 = h0 & HMASK;           // |h| per packed lane (alu pipe)
            ULL a1 = h1 & HMASK;
            acc0 = fma2(h0, HALF2, acc0);
            acc0 = fma2(a0, HALF2, acc0);
            acc1 = fma2(h1, HALF2, acc1);
            acc1 = fma2(a1, HALF2, acc1);
        }

        if (c == 0) {
            float* d = &es[1][rowoff(il) + q * 8];
            *(float2*)&d[0] = make_float2(v1.x, v1.x);
            *(float2*)&d[2] = make_float2(v1.y, v1.y);
            *(float2*)&d[4] = make_float2(v1.z, v1.z);
            *(float2*)&d[6] = make_float2(v1.w, v1.w);
            __syncthreads();
        }
    }

    float a0, a1, a2, a3;
    unpack2(acc0, a0, a1);     // h = hp, hp+32
    unpack2(acc1, a2, a3);     // h = hp+16, hp+48
    a0 += __shfl_xor_sync(0xffffffffu, a0, 16);
    a1 += __shfl_xor_sync(0xffffffffu, a1, 16);
    a2 += __shfl_xor_sync(0xffffffffu, a2, 16);
    a3 += __shfl_xor_sync(0xffffffffu, a3, 16);
    if ((t & 16) == 0) {
        atomicAdd(&hsum[hp],      a0);
        atomicAdd(&hsum[hp + 32], a1);
        atomicAdd(&hsum[hp + 16], a2);
        atomicAdd(&hsum[hp + 48], a3);
    }
    __syncthreads();
    if (t < 64) g_Hs[(half * 1024 + node) * 64 + t] = hsum[t];
}

// ============================================================================
// K2 (exact R6 best): grid 256 x 256 threads, 4 nodes/block.
// W2 slice register-resident; 4 independent 32-deep fma2 chains.
// ============================================================================
__global__ __launch_bounds__(256, 2)
void k_node(const float* __restrict__ x,
            const float* __restrict__ W2,
            const float* __restrict__ b2,
            const float* __restrict__ root,
            float* __restrict__ out) {
    __shared__ ULL   hs2[4 * 64];
    __shared__ float wpart[4 * 256];
    __shared__ float wsf[4 * 256];
    __shared__ float rb[256];
    __shared__ float xs[64];

    const int t     = threadIdx.x;
    const int node0 = blockIdx.x * 4;
    const int cp    = t & 127;
    const int ph    = t >> 7;

    {
        float hv = g_Hs[node0 * 64 + t] + g_Hs[1024 * 64 + node0 * 64 + t];
        hs2[t] = pack2(hv, hv);
    }
    rb[t] = 256.f * b2[t] + root[t];
    if (t < 64) xs[t] = x[node0 * 16 + t];

    ULL w2r[32];
    {
        const ULL* w2g = reinterpret_cast<const ULL*>(W2) + (ULL)(ph * 32) * 128 + cp;
        #pragma unroll
        for (int k = 0; k < 32; k++) w2r[k] = w2g[(ULL)k * 128];
    }
    __syncthreads();

    ULL acc[4];
    #pragma unroll
    for (int n = 0; n < 4; n++) acc[n] = pack2(0.f, 0.f);

    #pragma unroll
    for (int k = 0; k < 32; k++) {
        const ULL w = w2r[k];
        const int hh = ph * 32 + k;
        acc[0] = fma2(hs2[0 * 64 + hh], w, acc[0]);
        acc[1] = fma2(hs2[1 * 64 + hh], w, acc[1]);
        acc[2] = fma2(hs2[2 * 64 + hh], w, acc[2]);
        acc[3] = fma2(hs2[3 * 64 + hh], w, acc[3]);
    }

    if (ph == 0) {
        #pragma unroll
        for (int n = 0; n < 4; n++) {
            float lo, hi; unpack2(acc[n], lo, hi);
            wpart[n * 256 + 2 * cp]     = lo;
            wpart[n * 256 + 2 * cp + 1] = hi;
        }
    }
    __syncthreads();

    if (ph == 1) {
        #pragma unroll
        for (int n = 0; n < 4; n++) {
            float lo, hi; unpack2(acc[n], lo, hi);
            wsf[n * 256 + 2 * cp]     = lo + wpart[n * 256 + 2 * cp]     + rb[2 * cp];
            wsf[n * 256 + 2 * cp + 1] = hi + wpart[n * 256 + 2 * cp + 1] + rb[2 * cp + 1];
        }
    }
    __syncthreads();

    if (t < 64) {
        const int n = t >> 4, d = t & 15;
        float o = 0.f;
        #pragma unroll
        for (int c = 0; c < 16; c++)
            o += xs[n * 16 + c] * wsf[n * 256 + c * 16 + d];
        out[(node0 + n) * 16 + d] = o;
    }
}

extern "C" void kernel_launch(void* const* d_in, const int* in_sizes, int n_in,
                              void* d_out, int out_size) {
    const float* node_attr = (const float*)d_in[0];
    const float* edge_adj  = (const float*)d_in[1];
    const float* W1        = (const float*)d_in[2];
    const float* b1        = (const float*)d_in[3];
    const float* W2        = (const float*)d_in[4];
    const float* b2        = (const float*)d_in[5];
    const float* root      = (const float*)d_in[6];
    float* out = (float*)d_out;

    k_edge<<<2048, 128>>>(edge_adj, W1, b1);
    k_node<<<256, 256>>>(node_attr, W2, b2, root, out);
}